// round 12
// baseline (speedup 1.0000x reference)
#include <cuda_runtime.h>
#include <cuda_bf16.h>
#include <cstdint>

#define USER_NUM 80000
#define ITEM_NUM 40000
#define NTOT     (USER_NUM + ITEM_NUM)   // 120000
#define EMB      64
#define NNZ      1200000
#define N_LAYERS 3

#define TOTAL_F  (NTOT * EMB)            // 7,680,000 floats
#define TOTAL_V4 (TOTAL_F / 4)           // 1,920,000 float4

#define SCAN_BS  1024
#define NBLK     ((NTOT + SCAN_BS - 1) / SCAN_BS)   // 118

// Scratch (allocation-free rule: __device__ globals)
__device__ float g_bufA[TOTAL_F];
__device__ float g_bufB[TOTAL_F];
__device__ int   g_cnt[NTOT];
__device__ int   g_rowptr[NTOT + 1];
__device__ int   g_cursor[NTOT];
__device__ unsigned long long g_blk_desc[NBLK];   // (value<<32) | flag; 1=agg, 2=prefix
__device__ int2  g_sorted[NNZ];          // (col, val_bits), grouped by row — dense 9.6 MB

// ---------------------------------------------------------------------------
// zero: per-row counters + scan descriptors (one kernel)
// ---------------------------------------------------------------------------
__global__ void zero_kernel() {
    int i = blockIdx.x * blockDim.x + threadIdx.x;
    if (i < NTOT) g_cnt[i] = 0;
    if (i < NBLK) g_blk_desc[i] = 0ull;
}

// ---------------------------------------------------------------------------
// histogram of row counts
// ---------------------------------------------------------------------------
__global__ void hist_kernel(const int* __restrict__ rows) {
    int e = blockIdx.x * blockDim.x + threadIdx.x;
    if (e < NNZ) atomicAdd(&g_cnt[rows[e]], 1);
}

// ---------------------------------------------------------------------------
// Single-pass exclusive scan (decoupled lookback). All NBLK=118 blocks are
// co-resident (148 SMs), so spinning on predecessors cannot deadlock.
// Writes g_rowptr and g_cursor directly.
// ---------------------------------------------------------------------------
__global__ void scan_fused_kernel() {
    __shared__ int s[SCAN_BS];
    __shared__ int s_carry;
    int b = blockIdx.x, t = threadIdx.x;
    int i = b * SCAN_BS + t;
    int v = (i < NTOT) ? g_cnt[i] : 0;
    s[t] = v;
    __syncthreads();
    // inclusive scan within block
    for (int off = 1; off < SCAN_BS; off <<= 1) {
        int add = (t >= off) ? s[t - off] : 0;
        __syncthreads();
        s[t] += add;
        __syncthreads();
    }
    int total = s[SCAN_BS - 1];

    if (t == 0) {
        int ex = 0;
        if (b == 0) {
            // inclusive prefix == aggregate for block 0
            atomicExch(&g_blk_desc[0],
                       ((unsigned long long)(unsigned)total << 32) | 2ull);
        } else {
            // publish aggregate first so successors can make progress
            atomicExch(&g_blk_desc[b],
                       ((unsigned long long)(unsigned)total << 32) | 1ull);
            // lookback over predecessors
            int p = b - 1;
            while (true) {
                unsigned long long d;
                do {
                    d = *((volatile unsigned long long*)&g_blk_desc[p]);
                } while ((d & 3ull) == 0ull);
                ex += (int)(d >> 32);
                if ((d & 3ull) == 2ull) break;   // inclusive prefix found
                --p;
            }
            atomicExch(&g_blk_desc[b],
                       ((unsigned long long)(unsigned)(ex + total) << 32) | 2ull);
        }
        s_carry = ex;
        if (b == 0) g_rowptr[NTOT] = NNZ;
    }
    __syncthreads();

    int ex = s_carry;
    if (i < NTOT) {
        int rp = ex + s[t] - v;                  // global exclusive prefix
        g_rowptr[i] = rp;
        g_cursor[i] = rp;
    }
}

// ---------------------------------------------------------------------------
// scatter edges into row-grouped order
// ---------------------------------------------------------------------------
__global__ void scatter_kernel(const float* __restrict__ vals,
                               const int*   __restrict__ rows,
                               const int*   __restrict__ cols) {
    int e = blockIdx.x * blockDim.x + threadIdx.x;
    if (e >= NNZ) return;
    int r = rows[e];
    int pos = atomicAdd(&g_cursor[r], 1);
    int2 m;
    m.x = cols[e];
    m.y = __float_as_int(vals[e]);
    g_sorted[pos] = m;
}

// ---------------------------------------------------------------------------
// Fused CSR SpMM + layer accumulate.
// 16 threads per row; each thread owns one float4 column slice.
//   y[r] = sum_{e in row r} val * x[col]   (registers, unroll-2, dual acc)
//   out[r] (+)= y[r] / 3
// Gather source: col < split -> xa[col], else xb[col - split]
//   layer 0 : xa=user_emb, xb=item_emb, split=USER_NUM  (no init pass)
//   layer 1+: xa=xb=buf,   split=NTOT
// last==1 skips the y store. No atomics anywhere in the layers.
// ---------------------------------------------------------------------------
__global__ void spmm_fused_kernel(const float* __restrict__ xa,
                                  const float* __restrict__ xb,
                                  int split,
                                  float*       __restrict__ y,
                                  float4*      __restrict__ out4,
                                  int first, int last) {
    int t = blockIdx.x * blockDim.x + threadIdx.x;
    if (t >= NTOT * 16) return;
    int r = t >> 4;
    int c = (t & 15) * 4;

    int beg = __ldg(&g_rowptr[r]);
    int end = __ldg(&g_rowptr[r + 1]);

    float4 acc0 = make_float4(0.f, 0.f, 0.f, 0.f);
    float4 acc1 = make_float4(0.f, 0.f, 0.f, 0.f);

    int k = beg;
    for (; k + 2 <= end; k += 2) {
        int2 m0 = __ldg(&g_sorted[k]);
        int2 m1 = __ldg(&g_sorted[k + 1]);
        const float* p0 = (m0.x < split) ? xa + (size_t)m0.x * EMB
                                         : xb + (size_t)(m0.x - split) * EMB;
        const float* p1 = (m1.x < split) ? xa + (size_t)m1.x * EMB
                                         : xb + (size_t)(m1.x - split) * EMB;
        float4 xv0 = *reinterpret_cast<const float4*>(p0 + c);
        float4 xv1 = *reinterpret_cast<const float4*>(p1 + c);
        float v0 = __int_as_float(m0.y);
        float v1 = __int_as_float(m1.y);
        acc0.x += v0 * xv0.x; acc0.y += v0 * xv0.y;
        acc0.z += v0 * xv0.z; acc0.w += v0 * xv0.w;
        acc1.x += v1 * xv1.x; acc1.y += v1 * xv1.y;
        acc1.z += v1 * xv1.z; acc1.w += v1 * xv1.w;
    }
    if (k < end) {
        int2 m0 = __ldg(&g_sorted[k]);
        const float* p0 = (m0.x < split) ? xa + (size_t)m0.x * EMB
                                         : xb + (size_t)(m0.x - split) * EMB;
        float4 xv0 = *reinterpret_cast<const float4*>(p0 + c);
        float v0 = __int_as_float(m0.y);
        acc0.x += v0 * xv0.x; acc0.y += v0 * xv0.y;
        acc0.z += v0 * xv0.z; acc0.w += v0 * xv0.w;
    }

    float4 acc;
    acc.x = acc0.x + acc1.x; acc.y = acc0.y + acc1.y;
    acc.z = acc0.z + acc1.z; acc.w = acc0.w + acc1.w;

    size_t o = (size_t)t;                             // r*16 + lane
    if (!last) reinterpret_cast<float4*>(y)[o] = acc;

    const float inv3 = 1.0f / 3.0f;
    float4 res;
    if (first) {
        res.x = acc.x * inv3; res.y = acc.y * inv3;
        res.z = acc.z * inv3; res.w = acc.w * inv3;
    } else {
        float4 a = out4[o];
        res.x = a.x + acc.x * inv3; res.y = a.y + acc.y * inv3;
        res.z = a.z + acc.z * inv3; res.w = a.w + acc.w * inv3;
    }
    out4[o] = res;
}

// ---------------------------------------------------------------------------
// launch: 7 kernel launches, trivially graph-capturable.
// ---------------------------------------------------------------------------
extern "C" void kernel_launch(void* const* d_in, const int* in_sizes, int n_in,
                              void* d_out, int out_size) {
    const float* user_emb = (const float*)d_in[0];
    const float* item_emb = (const float*)d_in[1];
    const float* adj_vals = (const float*)d_in[2];
    const int*   adj_rows = (const int*)d_in[3];
    const int*   adj_cols = (const int*)d_in[4];
    float4* out = (float4*)d_out;

    float *A, *B;
    cudaGetSymbolAddress((void**)&A, g_bufA);
    cudaGetSymbolAddress((void**)&B, g_bufB);

    const int TB = 256;
    const int gridN = (NTOT + TB - 1) / TB;           // 469
    const int gridE = (NNZ + TB - 1) / TB;            // 4688
    const int gridS = (NTOT * 16 + TB - 1) / TB;      // 7500

    // CSR build (counting sort by row) — 4 kernels
    zero_kernel<<<gridN, TB>>>();
    hist_kernel<<<gridE, TB>>>(adj_rows);
    scan_fused_kernel<<<NBLK, SCAN_BS>>>();
    scatter_kernel<<<gridE, TB>>>(adj_vals, adj_rows, adj_cols);

    // Layer 0: gather straight from inputs -> B ; out  = B/3
    spmm_fused_kernel<<<gridS, TB>>>(user_emb, item_emb, USER_NUM, B, out, 1, 0);
    // Layer 1: B -> A ; out += A/3
    spmm_fused_kernel<<<gridS, TB>>>(B, B, NTOT, A, out, 0, 0);
    // Layer 2: A -> (skip store) ; out += y/3
    spmm_fused_kernel<<<gridS, TB>>>(A, A, NTOT, B, out, 0, 1);
}

// round 13
// speedup vs baseline: 1.0028x; 1.0028x over previous
#include <cuda_runtime.h>
#include <cuda_bf16.h>
#include <cstdint>

#define USER_NUM 80000
#define ITEM_NUM 40000
#define NTOT     (USER_NUM + ITEM_NUM)   // 120000
#define EMB      64
#define NNZ      1200000
#define N_LAYERS 3

#define TOTAL_F  (NTOT * EMB)            // 7,680,000 floats
#define TOTAL_V4 (TOTAL_F / 4)           // 1,920,000 float4

#define SCAN_BS  1024
#define NBLK     ((NTOT + SCAN_BS - 1) / SCAN_BS)   // 118

// Scratch (allocation-free rule: __device__ globals)
__device__ float g_bufA[TOTAL_F];
__device__ float g_bufB[TOTAL_F];
__device__ int   g_cnt[NTOT];
__device__ int   g_rowptr[NTOT + 1];
__device__ int   g_cursor[NTOT];
__device__ unsigned long long g_blk_desc[NBLK];   // (value<<32) | flag; 1=agg, 2=prefix
__device__ int2  g_sorted[NNZ];          // (col, val_bits), grouped by row — dense 9.6 MB

// ---------------------------------------------------------------------------
// zero: per-row counters + scan descriptors (one kernel)
// ---------------------------------------------------------------------------
__global__ void zero_kernel() {
    int i = blockIdx.x * blockDim.x + threadIdx.x;
    if (i < NTOT) g_cnt[i] = 0;
    if (i < NBLK) g_blk_desc[i] = 0ull;
}

// ---------------------------------------------------------------------------
// histogram of row counts — 4 edges/thread (int4 load) for MLP=4.
// NNZ % 4 == 0, input buffers are >=256B aligned.
// ---------------------------------------------------------------------------
__global__ void hist_kernel(const int4* __restrict__ rows4) {
    int t = blockIdx.x * blockDim.x + threadIdx.x;
    if (t >= NNZ / 4) return;
    int4 r = rows4[t];
    atomicAdd(&g_cnt[r.x], 1);
    atomicAdd(&g_cnt[r.y], 1);
    atomicAdd(&g_cnt[r.z], 1);
    atomicAdd(&g_cnt[r.w], 1);
}

// ---------------------------------------------------------------------------
// Single-pass exclusive scan (decoupled lookback), shuffle-based block scan.
// All NBLK=118 blocks are co-resident (148 SMs) — spin cannot deadlock.
// Writes g_rowptr and g_cursor directly.
// ---------------------------------------------------------------------------
__global__ void scan_fused_kernel() {
    __shared__ int s_warp[32];
    __shared__ int s_carry;
    int b = blockIdx.x, t = threadIdx.x;
    int lane = t & 31, w = t >> 5;
    int i = b * SCAN_BS + t;
    int v = (i < NTOT) ? g_cnt[i] : 0;

    // warp-inclusive scan via shuffles
    int x = v;
    #pragma unroll
    for (int off = 1; off < 32; off <<= 1) {
        int n = __shfl_up_sync(0xFFFFFFFFu, x, off);
        if (lane >= off) x += n;
    }
    if (lane == 31) s_warp[w] = x;
    __syncthreads();
    if (w == 0) {                         // scan the 32 warp totals
        int ws = s_warp[lane];
        #pragma unroll
        for (int off = 1; off < 32; off <<= 1) {
            int n = __shfl_up_sync(0xFFFFFFFFu, ws, off);
            if (lane >= off) ws += n;
        }
        s_warp[lane] = ws;
    }
    __syncthreads();
    int incl  = x + (w > 0 ? s_warp[w - 1] : 0);   // block-inclusive prefix
    int total = s_warp[31];

    if (t == 0) {
        int ex = 0;
        if (b == 0) {
            atomicExch(&g_blk_desc[0],
                       ((unsigned long long)(unsigned)total << 32) | 2ull);
            g_rowptr[NTOT] = NNZ;
        } else {
            atomicExch(&g_blk_desc[b],
                       ((unsigned long long)(unsigned)total << 32) | 1ull);
            int p = b - 1;
            while (true) {
                unsigned long long d;
                do {
                    d = *((volatile unsigned long long*)&g_blk_desc[p]);
                } while ((d & 3ull) == 0ull);
                ex += (int)(d >> 32);
                if ((d & 3ull) == 2ull) break;   // inclusive prefix found
                --p;
            }
            atomicExch(&g_blk_desc[b],
                       ((unsigned long long)(unsigned)(ex + total) << 32) | 2ull);
        }
        s_carry = ex;
    }
    __syncthreads();

    if (i < NTOT) {
        int rp = s_carry + incl - v;             // global exclusive prefix
        g_rowptr[i] = rp;
        g_cursor[i] = rp;
    }
}

// ---------------------------------------------------------------------------
// scatter edges into row-grouped order — 4 edges/thread for MLP=4.
// ---------------------------------------------------------------------------
__global__ void scatter_kernel(const float4* __restrict__ vals4,
                               const int4*   __restrict__ rows4,
                               const int4*   __restrict__ cols4) {
    int t = blockIdx.x * blockDim.x + threadIdx.x;
    if (t >= NNZ / 4) return;
    int4   r = rows4[t];
    int4   c = cols4[t];
    float4 v = vals4[t];

    int p0 = atomicAdd(&g_cursor[r.x], 1);
    int p1 = atomicAdd(&g_cursor[r.y], 1);
    int p2 = atomicAdd(&g_cursor[r.z], 1);
    int p3 = atomicAdd(&g_cursor[r.w], 1);

    g_sorted[p0] = make_int2(c.x, __float_as_int(v.x));
    g_sorted[p1] = make_int2(c.y, __float_as_int(v.y));
    g_sorted[p2] = make_int2(c.z, __float_as_int(v.z));
    g_sorted[p3] = make_int2(c.w, __float_as_int(v.w));
}

// ---------------------------------------------------------------------------
// Fused CSR SpMM + layer accumulate.
// 16 threads per row; each thread owns one float4 column slice.
//   y[r] = sum_{e in row r} val * x[col]   (registers, unroll-2, dual acc)
//   out[r] (+)= y[r] / 3
// Gather source: col < split -> xa[col], else xb[col - split]
//   layer 0 : xa=user_emb, xb=item_emb, split=USER_NUM  (no init pass)
//   layer 1+: xa=xb=buf,   split=NTOT
// last==1 skips the y store. No atomics anywhere in the layers.
// ---------------------------------------------------------------------------
__global__ void spmm_fused_kernel(const float* __restrict__ xa,
                                  const float* __restrict__ xb,
                                  int split,
                                  float*       __restrict__ y,
                                  float4*      __restrict__ out4,
                                  int first, int last) {
    int t = blockIdx.x * blockDim.x + threadIdx.x;
    if (t >= NTOT * 16) return;
    int r = t >> 4;
    int c = (t & 15) * 4;

    int beg = __ldg(&g_rowptr[r]);
    int end = __ldg(&g_rowptr[r + 1]);

    float4 acc0 = make_float4(0.f, 0.f, 0.f, 0.f);
    float4 acc1 = make_float4(0.f, 0.f, 0.f, 0.f);

    int k = beg;
    for (; k + 2 <= end; k += 2) {
        int2 m0 = __ldg(&g_sorted[k]);
        int2 m1 = __ldg(&g_sorted[k + 1]);
        const float* p0 = (m0.x < split) ? xa + (size_t)m0.x * EMB
                                         : xb + (size_t)(m0.x - split) * EMB;
        const float* p1 = (m1.x < split) ? xa + (size_t)m1.x * EMB
                                         : xb + (size_t)(m1.x - split) * EMB;
        float4 xv0 = *reinterpret_cast<const float4*>(p0 + c);
        float4 xv1 = *reinterpret_cast<const float4*>(p1 + c);
        float v0 = __int_as_float(m0.y);
        float v1 = __int_as_float(m1.y);
        acc0.x += v0 * xv0.x; acc0.y += v0 * xv0.y;
        acc0.z += v0 * xv0.z; acc0.w += v0 * xv0.w;
        acc1.x += v1 * xv1.x; acc1.y += v1 * xv1.y;
        acc1.z += v1 * xv1.z; acc1.w += v1 * xv1.w;
    }
    if (k < end) {
        int2 m0 = __ldg(&g_sorted[k]);
        const float* p0 = (m0.x < split) ? xa + (size_t)m0.x * EMB
                                         : xb + (size_t)(m0.x - split) * EMB;
        float4 xv0 = *reinterpret_cast<const float4*>(p0 + c);
        float v0 = __int_as_float(m0.y);
        acc0.x += v0 * xv0.x; acc0.y += v0 * xv0.y;
        acc0.z += v0 * xv0.z; acc0.w += v0 * xv0.w;
    }

    float4 acc;
    acc.x = acc0.x + acc1.x; acc.y = acc0.y + acc1.y;
    acc.z = acc0.z + acc1.z; acc.w = acc0.w + acc1.w;

    size_t o = (size_t)t;                             // r*16 + lane
    if (!last) reinterpret_cast<float4*>(y)[o] = acc;

    const float inv3 = 1.0f / 3.0f;
    float4 res;
    if (first) {
        res.x = acc.x * inv3; res.y = acc.y * inv3;
        res.z = acc.z * inv3; res.w = acc.w * inv3;
    } else {
        float4 a = out4[o];
        res.x = a.x + acc.x * inv3; res.y = a.y + acc.y * inv3;
        res.z = a.z + acc.z * inv3; res.w = a.w + acc.w * inv3;
    }
    out4[o] = res;
}

// ---------------------------------------------------------------------------
// launch: 7 kernel launches, trivially graph-capturable.
// ---------------------------------------------------------------------------
extern "C" void kernel_launch(void* const* d_in, const int* in_sizes, int n_in,
                              void* d_out, int out_size) {
    const float* user_emb = (const float*)d_in[0];
    const float* item_emb = (const float*)d_in[1];
    const float* adj_vals = (const float*)d_in[2];
    const int*   adj_rows = (const int*)d_in[3];
    const int*   adj_cols = (const int*)d_in[4];
    float4* out = (float4*)d_out;

    float *A, *B;
    cudaGetSymbolAddress((void**)&A, g_bufA);
    cudaGetSymbolAddress((void**)&B, g_bufB);

    const int TB = 256;
    const int gridN  = (NTOT + TB - 1) / TB;          // 469
    const int gridE4 = (NNZ / 4 + TB - 1) / TB;       // 1172
    const int gridS  = (NTOT * 16 + TB - 1) / TB;     // 7500

    // CSR build (counting sort by row) — 4 kernels
    zero_kernel<<<gridN, TB>>>();
    hist_kernel<<<gridE4, TB>>>((const int4*)adj_rows);
    scan_fused_kernel<<<NBLK, SCAN_BS>>>();
    scatter_kernel<<<gridE4, TB>>>((const float4*)adj_vals,
                                   (const int4*)adj_rows,
                                   (const int4*)adj_cols);

    // Layer 0: gather straight from inputs -> B ; out  = B/3
    spmm_fused_kernel<<<gridS, TB>>>(user_emb, item_emb, USER_NUM, B, out, 1, 0);
    // Layer 1: B -> A ; out += A/3
    spmm_fused_kernel<<<gridS, TB>>>(B, B, NTOT, A, out, 0, 0);
    // Layer 2: A -> (skip store) ; out += y/3
    spmm_fused_kernel<<<gridS, TB>>>(A, A, NTOT, B, out, 0, 1);
}

// round 14
// speedup vs baseline: 1.1240x; 1.1209x over previous
#include <cuda_runtime.h>
#include <cuda_bf16.h>
#include <cstdint>

#define USER_NUM 80000
#define ITEM_NUM 40000
#define NTOT     (USER_NUM + ITEM_NUM)   // 120000
#define EMB      64
#define NNZ      1200000
#define N_LAYERS 3

#define TOTAL_F  (NTOT * EMB)            // 7,680,000 floats
#define TOTAL_V4 (TOTAL_F / 4)           // 1,920,000 float4

#define SCAN_BS  1024
#define NBLK     ((NTOT + SCAN_BS - 1) / SCAN_BS)   // 118

// Scratch (allocation-free rule: __device__ globals)
__device__ float g_bufA[TOTAL_F];
__device__ float g_bufB[TOTAL_F];
__device__ int   g_cnt[NTOT];
__device__ int   g_rowptr[NTOT + 1];
__device__ int   g_pos[NNZ];             // within-row rank of each edge
__device__ unsigned long long g_blk_desc[NBLK];   // (value<<32) | flag; 1=agg, 2=prefix
__device__ int2  g_sorted[NNZ];          // (col, val_bits), grouped by row — dense 9.6 MB

// ---------------------------------------------------------------------------
// zero: per-row counters + scan descriptors (one kernel)
// ---------------------------------------------------------------------------
__global__ void zero_kernel() {
    int i = blockIdx.x * blockDim.x + threadIdx.x;
    if (i < NTOT) g_cnt[i] = 0;
    if (i < NBLK) g_blk_desc[i] = 0ull;
}

// ---------------------------------------------------------------------------
// hist + position in ONE atomic pass: pos[e] = cnt[row[e]]++ .
// The single atomicAdd yields both the histogram (for the scan) and the
// edge's within-row rank — the scatter needs no atomics afterwards.
// 4 edges/thread; pos stored as one coalesced int4.
// ---------------------------------------------------------------------------
__global__ void hist_pos_kernel(const int4* __restrict__ rows4) {
    int t = blockIdx.x * blockDim.x + threadIdx.x;
    if (t >= NNZ / 4) return;
    int4 r = rows4[t];
    int4 p;
    p.x = atomicAdd(&g_cnt[r.x], 1);
    p.y = atomicAdd(&g_cnt[r.y], 1);
    p.z = atomicAdd(&g_cnt[r.z], 1);
    p.w = atomicAdd(&g_cnt[r.w], 1);
    reinterpret_cast<int4*>(g_pos)[t] = p;
}

// ---------------------------------------------------------------------------
// Single-pass exclusive scan (decoupled lookback), shuffle-based block scan.
// All NBLK=118 blocks are co-resident (148 SMs) — spin cannot deadlock.
// ---------------------------------------------------------------------------
__global__ void scan_fused_kernel() {
    __shared__ int s_warp[32];
    __shared__ int s_carry;
    int b = blockIdx.x, t = threadIdx.x;
    int lane = t & 31, w = t >> 5;
    int i = b * SCAN_BS + t;
    int v = (i < NTOT) ? g_cnt[i] : 0;

    // warp-inclusive scan via shuffles
    int x = v;
    #pragma unroll
    for (int off = 1; off < 32; off <<= 1) {
        int n = __shfl_up_sync(0xFFFFFFFFu, x, off);
        if (lane >= off) x += n;
    }
    if (lane == 31) s_warp[w] = x;
    __syncthreads();
    if (w == 0) {                         // scan the 32 warp totals
        int ws = s_warp[lane];
        #pragma unroll
        for (int off = 1; off < 32; off <<= 1) {
            int n = __shfl_up_sync(0xFFFFFFFFu, ws, off);
            if (lane >= off) ws += n;
        }
        s_warp[lane] = ws;
    }
    __syncthreads();
    int incl  = x + (w > 0 ? s_warp[w - 1] : 0);   // block-inclusive prefix
    int total = s_warp[31];

    if (t == 0) {
        int ex = 0;
        if (b == 0) {
            atomicExch(&g_blk_desc[0],
                       ((unsigned long long)(unsigned)total << 32) | 2ull);
            g_rowptr[NTOT] = NNZ;
        } else {
            atomicExch(&g_blk_desc[b],
                       ((unsigned long long)(unsigned)total << 32) | 1ull);
            int p = b - 1;
            while (true) {
                unsigned long long d;
                do {
                    d = *((volatile unsigned long long*)&g_blk_desc[p]);
                } while ((d & 3ull) == 0ull);
                ex += (int)(d >> 32);
                if ((d & 3ull) == 2ull) break;   // inclusive prefix found
                --p;
            }
            atomicExch(&g_blk_desc[b],
                       ((unsigned long long)(unsigned)(ex + total) << 32) | 2ull);
        }
        s_carry = ex;
    }
    __syncthreads();

    if (i < NTOT) g_rowptr[i] = s_carry + incl - v;   // global exclusive prefix
}

// ---------------------------------------------------------------------------
// scatter (STREAMING, no atomics): g_sorted[rowptr[r] + pos[e]] = (col, val).
// 4 edges/thread; all loads coalesced, stores random 8B.
// ---------------------------------------------------------------------------
__global__ void scatter_kernel(const float4* __restrict__ vals4,
                               const int4*   __restrict__ rows4,
                               const int4*   __restrict__ cols4) {
    int t = blockIdx.x * blockDim.x + threadIdx.x;
    if (t >= NNZ / 4) return;
    int4   r = rows4[t];
    int4   c = cols4[t];
    float4 v = vals4[t];
    int4   p = reinterpret_cast<const int4*>(g_pos)[t];

    g_sorted[__ldg(&g_rowptr[r.x]) + p.x] = make_int2(c.x, __float_as_int(v.x));
    g_sorted[__ldg(&g_rowptr[r.y]) + p.y] = make_int2(c.y, __float_as_int(v.y));
    g_sorted[__ldg(&g_rowptr[r.z]) + p.z] = make_int2(c.z, __float_as_int(v.z));
    g_sorted[__ldg(&g_rowptr[r.w]) + p.w] = make_int2(c.w, __float_as_int(v.w));
}

// ---------------------------------------------------------------------------
// Fused CSR SpMM. 16 threads per row; each thread owns one float4 slice.
//   acc = sum_{e in row r} val * x[col]   (registers, unroll-2, dual acc)
// mode 0: store acc -> y                    (layers 0, 1)
// mode 1: out = (prevB[o] + prevA[o] + acc) / 3   (final layer; single write)
// Gather source: col < split -> xa[col], else xb[col - split]
//   layer 0 : xa=user_emb, xb=item_emb, split=USER_NUM  (no init pass)
//   layer 1+: xa=xb=buf,   split=NTOT
// ---------------------------------------------------------------------------
__global__ void spmm_fused_kernel(const float* __restrict__ xa,
                                  const float* __restrict__ xb,
                                  int split,
                                  float*       __restrict__ y,
                                  const float4* __restrict__ prevB,
                                  const float4* __restrict__ prevA,
                                  float4*      __restrict__ out4,
                                  int mode) {
    int t = blockIdx.x * blockDim.x + threadIdx.x;
    if (t >= NTOT * 16) return;
    int r = t >> 4;
    int c = (t & 15) * 4;

    int beg = __ldg(&g_rowptr[r]);
    int end = __ldg(&g_rowptr[r + 1]);

    float4 acc0 = make_float4(0.f, 0.f, 0.f, 0.f);
    float4 acc1 = make_float4(0.f, 0.f, 0.f, 0.f);

    int k = beg;
    for (; k + 2 <= end; k += 2) {
        int2 m0 = __ldg(&g_sorted[k]);
        int2 m1 = __ldg(&g_sorted[k + 1]);
        const float* p0 = (m0.x < split) ? xa + (size_t)m0.x * EMB
                                         : xb + (size_t)(m0.x - split) * EMB;
        const float* p1 = (m1.x < split) ? xa + (size_t)m1.x * EMB
                                         : xb + (size_t)(m1.x - split) * EMB;
        float4 xv0 = *reinterpret_cast<const float4*>(p0 + c);
        float4 xv1 = *reinterpret_cast<const float4*>(p1 + c);
        float v0 = __int_as_float(m0.y);
        float v1 = __int_as_float(m1.y);
        acc0.x += v0 * xv0.x; acc0.y += v0 * xv0.y;
        acc0.z += v0 * xv0.z; acc0.w += v0 * xv0.w;
        acc1.x += v1 * xv1.x; acc1.y += v1 * xv1.y;
        acc1.z += v1 * xv1.z; acc1.w += v1 * xv1.w;
    }
    if (k < end) {
        int2 m0 = __ldg(&g_sorted[k]);
        const float* p0 = (m0.x < split) ? xa + (size_t)m0.x * EMB
                                         : xb + (size_t)(m0.x - split) * EMB;
        float4 xv0 = *reinterpret_cast<const float4*>(p0 + c);
        float v0 = __int_as_float(m0.y);
        acc0.x += v0 * xv0.x; acc0.y += v0 * xv0.y;
        acc0.z += v0 * xv0.z; acc0.w += v0 * xv0.w;
    }

    float4 acc;
    acc.x = acc0.x + acc1.x; acc.y = acc0.y + acc1.y;
    acc.z = acc0.z + acc1.z; acc.w = acc0.w + acc1.w;

    size_t o = (size_t)t;                             // r*16 + lane
    if (mode == 0) {
        reinterpret_cast<float4*>(y)[o] = acc;
    } else {
        const float inv3 = 1.0f / 3.0f;
        float4 b1 = prevB[o];
        float4 a2 = prevA[o];
        float4 res;
        res.x = (b1.x + a2.x + acc.x) * inv3;
        res.y = (b1.y + a2.y + acc.y) * inv3;
        res.z = (b1.z + a2.z + acc.z) * inv3;
        res.w = (b1.w + a2.w + acc.w) * inv3;
        out4[o] = res;
    }
}

// ---------------------------------------------------------------------------
// launch: 7 kernel launches, trivially graph-capturable.
// ---------------------------------------------------------------------------
extern "C" void kernel_launch(void* const* d_in, const int* in_sizes, int n_in,
                              void* d_out, int out_size) {
    const float* user_emb = (const float*)d_in[0];
    const float* item_emb = (const float*)d_in[1];
    const float* adj_vals = (const float*)d_in[2];
    const int*   adj_rows = (const int*)d_in[3];
    const int*   adj_cols = (const int*)d_in[4];
    float4* out = (float4*)d_out;

    float *A, *B;
    cudaGetSymbolAddress((void**)&A, g_bufA);
    cudaGetSymbolAddress((void**)&B, g_bufB);

    const int TB = 256;
    const int gridN  = (NTOT + TB - 1) / TB;          // 469
    const int gridE4 = (NNZ / 4 + TB - 1) / TB;       // 1172
    const int gridS  = (NTOT * 16 + TB - 1) / TB;     // 7500

    // CSR build: zero, fused hist+pos (1.2M atomics total), scan, streaming scatter
    zero_kernel<<<gridN, TB>>>();
    hist_pos_kernel<<<gridE4, TB>>>((const int4*)adj_rows);
    scan_fused_kernel<<<NBLK, SCAN_BS>>>();
    scatter_kernel<<<gridE4, TB>>>((const float4*)adj_vals,
                                   (const int4*)adj_rows,
                                   (const int4*)adj_cols);

    // Layer 0: inputs -> B
    spmm_fused_kernel<<<gridS, TB>>>(user_emb, item_emb, USER_NUM, B,
                                     nullptr, nullptr, nullptr, 0);
    // Layer 1: B -> A
    spmm_fused_kernel<<<gridS, TB>>>(B, B, NTOT, A,
                                     nullptr, nullptr, nullptr, 0);
    // Layer 2: A -> acc ; out = (B + A + acc)/3   (single output write)
    spmm_fused_kernel<<<gridS, TB>>>(A, A, NTOT, nullptr,
                                     (const float4*)B, (const float4*)A, out, 1);
}

// round 15
// speedup vs baseline: 1.1287x; 1.0041x over previous
#include <cuda_runtime.h>
#include <cuda_fp16.h>
#include <cstdint>

#define USER_NUM 80000
#define ITEM_NUM 40000
#define NTOT     (USER_NUM + ITEM_NUM)   // 120000
#define EMB      64
#define NNZ      1200000
#define N_LAYERS 3

#define TOTAL_F  (NTOT * EMB)            // 7,680,000 elements

#define SCAN_BS  1024
#define NBLK     ((NTOT + SCAN_BS - 1) / SCAN_BS)   // 118

// Scratch (allocation-free rule: __device__ globals)
// Ego ping-pong buffers in fp16: row = 64 halves = 128 bytes.
__device__ __half g_bufA[TOTAL_F];
__device__ __half g_bufB[TOTAL_F];
__device__ int    g_cnt[NTOT];
__device__ int    g_rowptr[NTOT + 1];
__device__ int    g_pos[NNZ];            // within-row rank of each edge
__device__ unsigned long long g_blk_desc[NBLK];   // (value<<32)|flag; 1=agg, 2=prefix
__device__ int2   g_sorted[NNZ];         // (col, val_bits), grouped by row

// ---------------------------------------------------------------------------
// zero: per-row counters + scan descriptors
// ---------------------------------------------------------------------------
__global__ void zero_kernel() {
    int i = blockIdx.x * blockDim.x + threadIdx.x;
    if (i < NTOT) g_cnt[i] = 0;
    if (i < NBLK) g_blk_desc[i] = 0ull;
}

// ---------------------------------------------------------------------------
// hist + position in ONE atomic pass: pos[e] = cnt[row[e]]++ .
// ---------------------------------------------------------------------------
__global__ void hist_pos_kernel(const int4* __restrict__ rows4) {
    int t = blockIdx.x * blockDim.x + threadIdx.x;
    if (t >= NNZ / 4) return;
    int4 r = rows4[t];
    int4 p;
    p.x = atomicAdd(&g_cnt[r.x], 1);
    p.y = atomicAdd(&g_cnt[r.y], 1);
    p.z = atomicAdd(&g_cnt[r.z], 1);
    p.w = atomicAdd(&g_cnt[r.w], 1);
    reinterpret_cast<int4*>(g_pos)[t] = p;
}

// ---------------------------------------------------------------------------
// Single-pass exclusive scan (decoupled lookback), shuffle-based block scan.
// All NBLK=118 blocks co-resident (148 SMs) — spin cannot deadlock.
// ---------------------------------------------------------------------------
__global__ void scan_fused_kernel() {
    __shared__ int s_warp[32];
    __shared__ int s_carry;
    int b = blockIdx.x, t = threadIdx.x;
    int lane = t & 31, w = t >> 5;
    int i = b * SCAN_BS + t;
    int v = (i < NTOT) ? g_cnt[i] : 0;

    int x = v;
    #pragma unroll
    for (int off = 1; off < 32; off <<= 1) {
        int n = __shfl_up_sync(0xFFFFFFFFu, x, off);
        if (lane >= off) x += n;
    }
    if (lane == 31) s_warp[w] = x;
    __syncthreads();
    if (w == 0) {
        int ws = s_warp[lane];
        #pragma unroll
        for (int off = 1; off < 32; off <<= 1) {
            int n = __shfl_up_sync(0xFFFFFFFFu, ws, off);
            if (lane >= off) ws += n;
        }
        s_warp[lane] = ws;
    }
    __syncthreads();
    int incl  = x + (w > 0 ? s_warp[w - 1] : 0);
    int total = s_warp[31];

    if (t == 0) {
        int ex = 0;
        if (b == 0) {
            atomicExch(&g_blk_desc[0],
                       ((unsigned long long)(unsigned)total << 32) | 2ull);
            g_rowptr[NTOT] = NNZ;
        } else {
            atomicExch(&g_blk_desc[b],
                       ((unsigned long long)(unsigned)total << 32) | 1ull);
            int p = b - 1;
            while (true) {
                unsigned long long d;
                do {
                    d = *((volatile unsigned long long*)&g_blk_desc[p]);
                } while ((d & 3ull) == 0ull);
                ex += (int)(d >> 32);
                if ((d & 3ull) == 2ull) break;
                --p;
            }
            atomicExch(&g_blk_desc[b],
                       ((unsigned long long)(unsigned)(ex + total) << 32) | 2ull);
        }
        s_carry = ex;
    }
    __syncthreads();

    if (i < NTOT) g_rowptr[i] = s_carry + incl - v;
}

// ---------------------------------------------------------------------------
// scatter (STREAMING, no atomics): g_sorted[rowptr[r] + pos[e]] = (col, val).
// ---------------------------------------------------------------------------
__global__ void scatter_kernel(const float4* __restrict__ vals4,
                               const int4*   __restrict__ rows4,
                               const int4*   __restrict__ cols4) {
    int t = blockIdx.x * blockDim.x + threadIdx.x;
    if (t >= NNZ / 4) return;
    int4   r = rows4[t];
    int4   c = cols4[t];
    float4 v = vals4[t];
    int4   p = reinterpret_cast<const int4*>(g_pos)[t];

    g_sorted[__ldg(&g_rowptr[r.x]) + p.x] = make_int2(c.x, __float_as_int(v.x));
    g_sorted[__ldg(&g_rowptr[r.y]) + p.y] = make_int2(c.y, __float_as_int(v.y));
    g_sorted[__ldg(&g_rowptr[r.z]) + p.z] = make_int2(c.z, __float_as_int(v.z));
    g_sorted[__ldg(&g_rowptr[r.w]) + p.w] = make_int2(c.w, __float_as_int(v.w));
}

// ---------------------------------------------------------------------------
// helpers: half4 <-> float4 (half4 carried as uint2)
// ---------------------------------------------------------------------------
__device__ __forceinline__ uint2 f4_to_h4(float4 f) {
    __half2 h01 = __floats2half2_rn(f.x, f.y);
    __half2 h23 = __floats2half2_rn(f.z, f.w);
    uint2 u;
    u.x = *reinterpret_cast<unsigned*>(&h01);
    u.y = *reinterpret_cast<unsigned*>(&h23);
    return u;
}
__device__ __forceinline__ float4 h4_to_f4(uint2 u) {
    __half2 h01 = *reinterpret_cast<__half2*>(&u.x);
    __half2 h23 = *reinterpret_cast<__half2*>(&u.y);
    float2 f01 = __half22float2(h01);
    float2 f23 = __half22float2(h23);
    return make_float4(f01.x, f01.y, f23.x, f23.y);
}

// ---------------------------------------------------------------------------
// Layer 0: gather fp32 inputs (split user/item), store fp16 y.
// 16 threads per row; lane owns 4 columns (16B fp32 gather, 8B fp16 store).
// ---------------------------------------------------------------------------
__global__ void spmm_l0_kernel(const float* __restrict__ xa,
                               const float* __restrict__ xb,
                               __half*      __restrict__ y) {
    int t = blockIdx.x * blockDim.x + threadIdx.x;
    if (t >= NTOT * 16) return;
    int r = t >> 4;
    int c = (t & 15) * 4;

    int beg = __ldg(&g_rowptr[r]);
    int end = __ldg(&g_rowptr[r + 1]);

    float4 acc0 = make_float4(0.f, 0.f, 0.f, 0.f);
    float4 acc1 = make_float4(0.f, 0.f, 0.f, 0.f);

    int k = beg;
    for (; k + 2 <= end; k += 2) {
        int2 m0 = __ldg(&g_sorted[k]);
        int2 m1 = __ldg(&g_sorted[k + 1]);
        const float* p0 = (m0.x < USER_NUM) ? xa + (size_t)m0.x * EMB
                                            : xb + (size_t)(m0.x - USER_NUM) * EMB;
        const float* p1 = (m1.x < USER_NUM) ? xa + (size_t)m1.x * EMB
                                            : xb + (size_t)(m1.x - USER_NUM) * EMB;
        float4 xv0 = *reinterpret_cast<const float4*>(p0 + c);
        float4 xv1 = *reinterpret_cast<const float4*>(p1 + c);
        float v0 = __int_as_float(m0.y);
        float v1 = __int_as_float(m1.y);
        acc0.x += v0 * xv0.x; acc0.y += v0 * xv0.y;
        acc0.z += v0 * xv0.z; acc0.w += v0 * xv0.w;
        acc1.x += v1 * xv1.x; acc1.y += v1 * xv1.y;
        acc1.z += v1 * xv1.z; acc1.w += v1 * xv1.w;
    }
    if (k < end) {
        int2 m0 = __ldg(&g_sorted[k]);
        const float* p0 = (m0.x < USER_NUM) ? xa + (size_t)m0.x * EMB
                                            : xb + (size_t)(m0.x - USER_NUM) * EMB;
        float4 xv0 = *reinterpret_cast<const float4*>(p0 + c);
        float v0 = __int_as_float(m0.y);
        acc0.x += v0 * xv0.x; acc0.y += v0 * xv0.y;
        acc0.z += v0 * xv0.z; acc0.w += v0 * xv0.w;
    }

    float4 acc;
    acc.x = acc0.x + acc1.x; acc.y = acc0.y + acc1.y;
    acc.z = acc0.z + acc1.z; acc.w = acc0.w + acc1.w;

    reinterpret_cast<uint2*>(y)[t] = f4_to_h4(acc);
}

// ---------------------------------------------------------------------------
// Layers 1..2: gather fp16 (row = 128B), accumulate fp32.
// mode 0: store fp16 y.
// mode 1: out = (pB[o] + pA[o] + acc) / 3  (fp32 output, single write)
// ---------------------------------------------------------------------------
__global__ void spmm_l12_kernel(const __half* __restrict__ x,
                                __half*       __restrict__ y,
                                const __half* __restrict__ pB,
                                const __half* __restrict__ pA,
                                float4*       __restrict__ out4,
                                int mode) {
    int t = blockIdx.x * blockDim.x + threadIdx.x;
    if (t >= NTOT * 16) return;
    int r = t >> 4;
    int c = (t & 15) * 4;          // column offset in elements

    int beg = __ldg(&g_rowptr[r]);
    int end = __ldg(&g_rowptr[r + 1]);

    float4 acc0 = make_float4(0.f, 0.f, 0.f, 0.f);
    float4 acc1 = make_float4(0.f, 0.f, 0.f, 0.f);

    int k = beg;
    for (; k + 2 <= end; k += 2) {
        int2 m0 = __ldg(&g_sorted[k]);
        int2 m1 = __ldg(&g_sorted[k + 1]);
        uint2 u0 = *reinterpret_cast<const uint2*>(x + (size_t)m0.x * EMB + c);
        uint2 u1 = *reinterpret_cast<const uint2*>(x + (size_t)m1.x * EMB + c);
        float4 xv0 = h4_to_f4(u0);
        float4 xv1 = h4_to_f4(u1);
        float v0 = __int_as_float(m0.y);
        float v1 = __int_as_float(m1.y);
        acc0.x += v0 * xv0.x; acc0.y += v0 * xv0.y;
        acc0.z += v0 * xv0.z; acc0.w += v0 * xv0.w;
        acc1.x += v1 * xv1.x; acc1.y += v1 * xv1.y;
        acc1.z += v1 * xv1.z; acc1.w += v1 * xv1.w;
    }
    if (k < end) {
        int2 m0 = __ldg(&g_sorted[k]);
        uint2 u0 = *reinterpret_cast<const uint2*>(x + (size_t)m0.x * EMB + c);
        float4 xv0 = h4_to_f4(u0);
        float v0 = __int_as_float(m0.y);
        acc0.x += v0 * xv0.x; acc0.y += v0 * xv0.y;
        acc0.z += v0 * xv0.z; acc0.w += v0 * xv0.w;
    }

    float4 acc;
    acc.x = acc0.x + acc1.x; acc.y = acc0.y + acc1.y;
    acc.z = acc0.z + acc1.z; acc.w = acc0.w + acc1.w;

    size_t o = (size_t)t;
    if (mode == 0) {
        reinterpret_cast<uint2*>(y)[o] = f4_to_h4(acc);
    } else {
        float4 b1 = h4_to_f4(reinterpret_cast<const uint2*>(pB)[o]);
        float4 a2 = h4_to_f4(reinterpret_cast<const uint2*>(pA)[o]);
        const float inv3 = 1.0f / 3.0f;
        float4 res;
        res.x = (b1.x + a2.x + acc.x) * inv3;
        res.y = (b1.y + a2.y + acc.y) * inv3;
        res.z = (b1.z + a2.z + acc.z) * inv3;
        res.w = (b1.w + a2.w + acc.w) * inv3;
        out4[o] = res;
    }
}

// ---------------------------------------------------------------------------
// launch: 7 kernel launches, trivially graph-capturable.
// ---------------------------------------------------------------------------
extern "C" void kernel_launch(void* const* d_in, const int* in_sizes, int n_in,
                              void* d_out, int out_size) {
    const float* user_emb = (const float*)d_in[0];
    const float* item_emb = (const float*)d_in[1];
    const float* adj_vals = (const float*)d_in[2];
    const int*   adj_rows = (const int*)d_in[3];
    const int*   adj_cols = (const int*)d_in[4];
    float4* out = (float4*)d_out;

    __half *A, *B;
    cudaGetSymbolAddress((void**)&A, g_bufA);
    cudaGetSymbolAddress((void**)&B, g_bufB);

    const int TB = 256;
    const int gridN  = (NTOT + TB - 1) / TB;          // 469
    const int gridE4 = (NNZ / 4 + TB - 1) / TB;       // 1172
    const int gridS  = (NTOT * 16 + TB - 1) / TB;     // 7500

    // CSR build: zero, fused hist+pos (1.2M atomics), scan, streaming scatter
    zero_kernel<<<gridN, TB>>>();
    hist_pos_kernel<<<gridE4, TB>>>((const int4*)adj_rows);
    scan_fused_kernel<<<NBLK, SCAN_BS>>>();
    scatter_kernel<<<gridE4, TB>>>((const float4*)adj_vals,
                                   (const int4*)adj_rows,
                                   (const int4*)adj_cols);

    // Layer 0: fp32 inputs -> fp16 B
    spmm_l0_kernel<<<gridS, TB>>>(user_emb, item_emb, B);
    // Layer 1: fp16 B -> fp16 A
    spmm_l12_kernel<<<gridS, TB>>>(B, A, nullptr, nullptr, nullptr, 0);
    // Layer 2: fp16 A -> acc ; out = (B + A + acc)/3  (fp32, single write)
    spmm_l12_kernel<<<gridS, TB>>>(A, nullptr, B, A, out, 1);
}

// round 16
// speedup vs baseline: 1.1418x; 1.0116x over previous
#include <cuda_runtime.h>
#include <cuda_fp16.h>
#include <cstdint>

#define USER_NUM 80000
#define ITEM_NUM 40000
#define NTOT     (USER_NUM + ITEM_NUM)   // 120000
#define EMB      64
#define NNZ      1200000
#define N_LAYERS 3

#define TOTAL_F  (NTOT * EMB)            // 7,680,000 elements

#define SCAN_BS  1024
#define NBLK     ((NTOT + SCAN_BS - 1) / SCAN_BS)   // 118

// Scratch (allocation-free rule: __device__ globals)
// Ego ping-pong buffers in fp16: row = 64 halves = 128 bytes.
__device__ __half g_bufA[TOTAL_F];
__device__ __half g_bufB[TOTAL_F];
__device__ int    g_cnt[NTOT];
__device__ int    g_rowptr[NTOT + 1];
__device__ int    g_pos[NNZ];            // within-row rank of each edge
__device__ unsigned long long g_blk_desc[NBLK];   // (value<<32)|flag; 1=agg, 2=prefix
__device__ int2   g_sorted[NNZ];         // (col, val_bits), grouped by row

// ---------------------------------------------------------------------------
// zero: per-row counters + scan descriptors
// ---------------------------------------------------------------------------
__global__ void zero_kernel() {
    int i = blockIdx.x * blockDim.x + threadIdx.x;
    if (i < NTOT) g_cnt[i] = 0;
    if (i < NBLK) g_blk_desc[i] = 0ull;
}

// ---------------------------------------------------------------------------
// hist + position in ONE atomic pass: pos[e] = cnt[row[e]]++ .
// ---------------------------------------------------------------------------
__global__ void hist_pos_kernel(const int4* __restrict__ rows4) {
    int t = blockIdx.x * blockDim.x + threadIdx.x;
    if (t >= NNZ / 4) return;
    int4 r = rows4[t];
    int4 p;
    p.x = atomicAdd(&g_cnt[r.x], 1);
    p.y = atomicAdd(&g_cnt[r.y], 1);
    p.z = atomicAdd(&g_cnt[r.z], 1);
    p.w = atomicAdd(&g_cnt[r.w], 1);
    reinterpret_cast<int4*>(g_pos)[t] = p;
}

// ---------------------------------------------------------------------------
// Single-pass exclusive scan (decoupled lookback), shuffle-based block scan.
// ---------------------------------------------------------------------------
__global__ void scan_fused_kernel() {
    __shared__ int s_warp[32];
    __shared__ int s_carry;
    int b = blockIdx.x, t = threadIdx.x;
    int lane = t & 31, w = t >> 5;
    int i = b * SCAN_BS + t;
    int v = (i < NTOT) ? g_cnt[i] : 0;

    int x = v;
    #pragma unroll
    for (int off = 1; off < 32; off <<= 1) {
        int n = __shfl_up_sync(0xFFFFFFFFu, x, off);
        if (lane >= off) x += n;
    }
    if (lane == 31) s_warp[w] = x;
    __syncthreads();
    if (w == 0) {
        int ws = s_warp[lane];
        #pragma unroll
        for (int off = 1; off < 32; off <<= 1) {
            int n = __shfl_up_sync(0xFFFFFFFFu, ws, off);
            if (lane >= off) ws += n;
        }
        s_warp[lane] = ws;
    }
    __syncthreads();
    int incl  = x + (w > 0 ? s_warp[w - 1] : 0);
    int total = s_warp[31];

    if (t == 0) {
        int ex = 0;
        if (b == 0) {
            atomicExch(&g_blk_desc[0],
                       ((unsigned long long)(unsigned)total << 32) | 2ull);
            g_rowptr[NTOT] = NNZ;
        } else {
            atomicExch(&g_blk_desc[b],
                       ((unsigned long long)(unsigned)total << 32) | 1ull);
            int p = b - 1;
            while (true) {
                unsigned long long d;
                do {
                    d = *((volatile unsigned long long*)&g_blk_desc[p]);
                } while ((d & 3ull) == 0ull);
                ex += (int)(d >> 32);
                if ((d & 3ull) == 2ull) break;
                --p;
            }
            atomicExch(&g_blk_desc[b],
                       ((unsigned long long)(unsigned)(ex + total) << 32) | 2ull);
        }
        s_carry = ex;
    }
    __syncthreads();

    if (i < NTOT) g_rowptr[i] = s_carry + incl - v;
}

// ---------------------------------------------------------------------------
// scatter (STREAMING, no atomics): g_sorted[rowptr[r] + pos[e]] = (col, val).
// ---------------------------------------------------------------------------
__global__ void scatter_kernel(const float4* __restrict__ vals4,
                               const int4*   __restrict__ rows4,
                               const int4*   __restrict__ cols4) {
    int t = blockIdx.x * blockDim.x + threadIdx.x;
    if (t >= NNZ / 4) return;
    int4   r = rows4[t];
    int4   c = cols4[t];
    float4 v = vals4[t];
    int4   p = reinterpret_cast<const int4*>(g_pos)[t];

    g_sorted[__ldg(&g_rowptr[r.x]) + p.x] = make_int2(c.x, __float_as_int(v.x));
    g_sorted[__ldg(&g_rowptr[r.y]) + p.y] = make_int2(c.y, __float_as_int(v.y));
    g_sorted[__ldg(&g_rowptr[r.z]) + p.z] = make_int2(c.z, __float_as_int(v.z));
    g_sorted[__ldg(&g_rowptr[r.w]) + p.w] = make_int2(c.w, __float_as_int(v.w));
}

// ---------------------------------------------------------------------------
// helpers
// ---------------------------------------------------------------------------
__device__ __forceinline__ uint2 f4_to_h4(float4 f) {
    __half2 h01 = __floats2half2_rn(f.x, f.y);
    __half2 h23 = __floats2half2_rn(f.z, f.w);
    uint2 u;
    u.x = *reinterpret_cast<unsigned*>(&h01);
    u.y = *reinterpret_cast<unsigned*>(&h23);
    return u;
}
// 8 halves (uint4) -> 8 floats, fma into acc[0..1] with scale v
__device__ __forceinline__ void h8_fma(float4& accA, float4& accB, uint4 u, float v) {
    __half2 h0 = *reinterpret_cast<__half2*>(&u.x);
    __half2 h1 = *reinterpret_cast<__half2*>(&u.y);
    __half2 h2 = *reinterpret_cast<__half2*>(&u.z);
    __half2 h3 = *reinterpret_cast<__half2*>(&u.w);
    float2 f0 = __half22float2(h0), f1 = __half22float2(h1);
    float2 f2 = __half22float2(h2), f3 = __half22float2(h3);
    accA.x += v * f0.x; accA.y += v * f0.y; accA.z += v * f1.x; accA.w += v * f1.y;
    accB.x += v * f2.x; accB.y += v * f2.y; accB.z += v * f3.x; accB.w += v * f3.y;
}

// ---------------------------------------------------------------------------
// Layer 0: gather fp32 inputs (split user/item), store fp16 y.
// 16 lanes/row; unroll-4 with paired int4 meta loads (2 edges / LDG.128).
// ---------------------------------------------------------------------------
__global__ void spmm_l0_kernel(const float* __restrict__ xa,
                               const float* __restrict__ xb,
                               __half*      __restrict__ y) {
    int t = blockIdx.x * blockDim.x + threadIdx.x;
    if (t >= NTOT * 16) return;
    int r = t >> 4;
    int c = (t & 15) * 4;

    int beg = __ldg(&g_rowptr[r]);
    int end = __ldg(&g_rowptr[r + 1]);

    float4 acc0 = make_float4(0.f, 0.f, 0.f, 0.f);
    float4 acc1 = make_float4(0.f, 0.f, 0.f, 0.f);

    int k = beg;
    // align k to even for int4 meta loads
    if (k < end && (k & 1)) {
        int2 m = __ldg(&g_sorted[k]);
        const float* p = (m.x < USER_NUM) ? xa + (size_t)m.x * EMB
                                          : xb + (size_t)(m.x - USER_NUM) * EMB;
        float4 xv = *reinterpret_cast<const float4*>(p + c);
        float v = __int_as_float(m.y);
        acc0.x += v * xv.x; acc0.y += v * xv.y;
        acc0.z += v * xv.z; acc0.w += v * xv.w;
        ++k;
    }
    for (; k + 4 <= end; k += 4) {
        int4 mA = __ldg(reinterpret_cast<const int4*>(&g_sorted[k]));
        int4 mB = __ldg(reinterpret_cast<const int4*>(&g_sorted[k + 2]));
        const float* p0 = (mA.x < USER_NUM) ? xa + (size_t)mA.x * EMB
                                            : xb + (size_t)(mA.x - USER_NUM) * EMB;
        const float* p1 = (mA.z < USER_NUM) ? xa + (size_t)mA.z * EMB
                                            : xb + (size_t)(mA.z - USER_NUM) * EMB;
        const float* p2 = (mB.x < USER_NUM) ? xa + (size_t)mB.x * EMB
                                            : xb + (size_t)(mB.x - USER_NUM) * EMB;
        const float* p3 = (mB.z < USER_NUM) ? xa + (size_t)mB.z * EMB
                                            : xb + (size_t)(mB.z - USER_NUM) * EMB;
        float4 x0 = *reinterpret_cast<const float4*>(p0 + c);
        float4 x1 = *reinterpret_cast<const float4*>(p1 + c);
        float4 x2 = *reinterpret_cast<const float4*>(p2 + c);
        float4 x3 = *reinterpret_cast<const float4*>(p3 + c);
        float v0 = __int_as_float(mA.y), v1 = __int_as_float(mA.w);
        float v2 = __int_as_float(mB.y), v3 = __int_as_float(mB.w);
        acc0.x += v0 * x0.x; acc0.y += v0 * x0.y; acc0.z += v0 * x0.z; acc0.w += v0 * x0.w;
        acc1.x += v1 * x1.x; acc1.y += v1 * x1.y; acc1.z += v1 * x1.z; acc1.w += v1 * x1.w;
        acc0.x += v2 * x2.x; acc0.y += v2 * x2.y; acc0.z += v2 * x2.z; acc0.w += v2 * x2.w;
        acc1.x += v3 * x3.x; acc1.y += v3 * x3.y; acc1.z += v3 * x3.z; acc1.w += v3 * x3.w;
    }
    for (; k < end; ++k) {
        int2 m = __ldg(&g_sorted[k]);
        const float* p = (m.x < USER_NUM) ? xa + (size_t)m.x * EMB
                                          : xb + (size_t)(m.x - USER_NUM) * EMB;
        float4 xv = *reinterpret_cast<const float4*>(p + c);
        float v = __int_as_float(m.y);
        acc0.x += v * xv.x; acc0.y += v * xv.y;
        acc0.z += v * xv.z; acc0.w += v * xv.w;
    }

    float4 acc;
    acc.x = acc0.x + acc1.x; acc.y = acc0.y + acc1.y;
    acc.z = acc0.z + acc1.z; acc.w = acc0.w + acc1.w;

    reinterpret_cast<uint2*>(y)[t] = f4_to_h4(acc);
}

// ---------------------------------------------------------------------------
// Layers 1..2: gather fp16, 8 lanes/row (16B/lane), 4 rows per warp.
// Unroll-2 with paired int4 meta loads.
// mode 0: store fp16 y (uint4/thread).
// mode 1: out = (pB + pA + acc) / 3  (fp32, 2x float4 per thread)
// ---------------------------------------------------------------------------
__global__ void spmm_l12_kernel(const __half* __restrict__ x,
                                __half*       __restrict__ y,
                                const __half* __restrict__ pB,
                                const __half* __restrict__ pA,
                                float4*       __restrict__ out4,
                                int mode) {
    int t = blockIdx.x * blockDim.x + threadIdx.x;
    if (t >= NTOT * 8) return;
    int r = t >> 3;
    int c = (t & 7) * 8;           // column offset in halves (8 per lane)

    int beg = __ldg(&g_rowptr[r]);
    int end = __ldg(&g_rowptr[r + 1]);

    float4 a0A = make_float4(0.f, 0.f, 0.f, 0.f);
    float4 a0B = make_float4(0.f, 0.f, 0.f, 0.f);
    float4 a1A = make_float4(0.f, 0.f, 0.f, 0.f);
    float4 a1B = make_float4(0.f, 0.f, 0.f, 0.f);

    int k = beg;
    if (k < end && (k & 1)) {
        int2 m = __ldg(&g_sorted[k]);
        uint4 u = *reinterpret_cast<const uint4*>(x + (size_t)m.x * EMB + c);
        h8_fma(a0A, a0B, u, __int_as_float(m.y));
        ++k;
    }
    for (; k + 2 <= end; k += 2) {
        int4 mm = __ldg(reinterpret_cast<const int4*>(&g_sorted[k]));
        uint4 u0 = *reinterpret_cast<const uint4*>(x + (size_t)mm.x * EMB + c);
        uint4 u1 = *reinterpret_cast<const uint4*>(x + (size_t)mm.z * EMB + c);
        h8_fma(a0A, a0B, u0, __int_as_float(mm.y));
        h8_fma(a1A, a1B, u1, __int_as_float(mm.w));
    }
    if (k < end) {
        int2 m = __ldg(&g_sorted[k]);
        uint4 u = *reinterpret_cast<const uint4*>(x + (size_t)m.x * EMB + c);
        h8_fma(a0A, a0B, u, __int_as_float(m.y));
    }

    float4 accA, accB;
    accA.x = a0A.x + a1A.x; accA.y = a0A.y + a1A.y;
    accA.z = a0A.z + a1A.z; accA.w = a0A.w + a1A.w;
    accB.x = a0B.x + a1B.x; accB.y = a0B.y + a1B.y;
    accB.z = a0B.z + a1B.z; accB.w = a0B.w + a1B.w;

    if (mode == 0) {
        uint2 lo = f4_to_h4(accA);
        uint2 hi = f4_to_h4(accB);
        uint4 st; st.x = lo.x; st.y = lo.y; st.z = hi.x; st.w = hi.y;
        reinterpret_cast<uint4*>(y)[t] = st;
    } else {
        // fp32 output: thread covers row r, cols c..c+7 -> out4[r*16 + (t&7)*2 .. +1]
        uint4 ub = reinterpret_cast<const uint4*>(pB)[t];
        uint4 ua = reinterpret_cast<const uint4*>(pA)[t];
        float4 bA = make_float4(0.f,0.f,0.f,0.f), bB = make_float4(0.f,0.f,0.f,0.f);
        float4 aA = make_float4(0.f,0.f,0.f,0.f), aB = make_float4(0.f,0.f,0.f,0.f);
        h8_fma(bA, bB, ub, 1.0f);
        h8_fma(aA, aB, ua, 1.0f);
        const float inv3 = 1.0f / 3.0f;
        float4 r0, r1;
        r0.x = (bA.x + aA.x + accA.x) * inv3;
        r0.y = (bA.y + aA.y + accA.y) * inv3;
        r0.z = (bA.z + aA.z + accA.z) * inv3;
        r0.w = (bA.w + aA.w + accA.w) * inv3;
        r1.x = (bB.x + aB.x + accB.x) * inv3;
        r1.y = (bB.y + aB.y + accB.y) * inv3;
        r1.z = (bB.z + aB.z + accB.z) * inv3;
        r1.w = (bB.w + aB.w + accB.w) * inv3;
        size_t o = (size_t)r * 16 + (size_t)(t & 7) * 2;
        out4[o]     = r0;
        out4[o + 1] = r1;
    }
}

// ---------------------------------------------------------------------------
// launch: 7 kernel launches, trivially graph-capturable.
// ---------------------------------------------------------------------------
extern "C" void kernel_launch(void* const* d_in, const int* in_sizes, int n_in,
                              void* d_out, int out_size) {
    const float* user_emb = (const float*)d_in[0];
    const float* item_emb = (const float*)d_in[1];
    const float* adj_vals = (const float*)d_in[2];
    const int*   adj_rows = (const int*)d_in[3];
    const int*   adj_cols = (const int*)d_in[4];
    float4* out = (float4*)d_out;

    __half *A, *B;
    cudaGetSymbolAddress((void**)&A, g_bufA);
    cudaGetSymbolAddress((void**)&B, g_bufB);

    const int TB = 256;
    const int gridN  = (NTOT + TB - 1) / TB;          // 469
    const int gridE4 = (NNZ / 4 + TB - 1) / TB;       // 1172
    const int gridS0 = (NTOT * 16 + TB - 1) / TB;     // 7500
    const int gridS1 = (NTOT * 8  + TB - 1) / TB;     // 3750

    // CSR build: zero, fused hist+pos (1.2M atomics), scan, streaming scatter
    zero_kernel<<<gridN, TB>>>();
    hist_pos_kernel<<<gridE4, TB>>>((const int4*)adj_rows);
    scan_fused_kernel<<<NBLK, SCAN_BS>>>();
    scatter_kernel<<<gridE4, TB>>>((const float4*)adj_vals,
                                   (const int4*)adj_rows,
                                   (const int4*)adj_cols);

    // Layer 0: fp32 inputs -> fp16 B
    spmm_l0_kernel<<<gridS0, TB>>>(user_emb, item_emb, B);
    // Layer 1: fp16 B -> fp16 A
    spmm_l12_kernel<<<gridS1, TB>>>(B, A, nullptr, nullptr, nullptr, 0);
    // Layer 2: fp16 A -> acc ; out = (B + A + acc)/3  (fp32, single write)
    spmm_l12_kernel<<<gridS1, TB>>>(A, nullptr, B, A, out, 1);
}

// round 17
// speedup vs baseline: 1.1796x; 1.0331x over previous
#include <cuda_runtime.h>
#include <cuda_fp16.h>
#include <cstdint>

#define USER_NUM 80000
#define ITEM_NUM 40000
#define NTOT     (USER_NUM + ITEM_NUM)   // 120000
#define EMB      64
#define NNZ      1200000
#define N_LAYERS 3

#define TOTAL_F  (NTOT * EMB)            // 7,680,000 elements
#define USER_F   (USER_NUM * EMB)        // 5,120,000 (divisible by 8)

#define SCAN_BS  1024
#define NBLK     ((NTOT + SCAN_BS - 1) / SCAN_BS)   // 118

// Scratch (allocation-free rule: __device__ globals)
// fp16 ego buffers: row = 64 halves = 128 bytes.
__device__ __half g_bufA[TOTAL_F];
__device__ __half g_bufB[TOTAL_F];
__device__ __half g_bufC[TOTAL_F];       // fp16 copy of the input embeddings
__device__ int    g_cnt[NTOT];
__device__ int    g_rowptr[NTOT + 1];
__device__ int    g_pos[NNZ];            // within-row rank of each edge
__device__ unsigned long long g_blk_desc[NBLK];   // (value<<32)|flag; 1=agg, 2=prefix
__device__ int2   g_sorted[NNZ];         // (col, val_bits), grouped by row

// ---------------------------------------------------------------------------
// convert inputs to fp16 (streaming) + zero counters/descriptors (folded in).
// One thread = 8 elements: 2x float4 load -> 1x uint4 store.
// ---------------------------------------------------------------------------
__global__ void convert_zero_kernel(const float4* __restrict__ user4,
                                    const float4* __restrict__ item4) {
    int i = blockIdx.x * blockDim.x + threadIdx.x;
    if (i < NTOT) g_cnt[i] = 0;
    if (i < NBLK) g_blk_desc[i] = 0ull;
    if (i >= TOTAL_F / 8) return;

    const int user_q = USER_F / 8;       // 640,000
    float4 f0, f1;
    if (i < user_q) {
        f0 = user4[i * 2];
        f1 = user4[i * 2 + 1];
    } else {
        int j = i - user_q;
        f0 = item4[j * 2];
        f1 = item4[j * 2 + 1];
    }
    __half2 h0 = __floats2half2_rn(f0.x, f0.y);
    __half2 h1 = __floats2half2_rn(f0.z, f0.w);
    __half2 h2 = __floats2half2_rn(f1.x, f1.y);
    __half2 h3 = __floats2half2_rn(f1.z, f1.w);
    uint4 u;
    u.x = *reinterpret_cast<unsigned*>(&h0);
    u.y = *reinterpret_cast<unsigned*>(&h1);
    u.z = *reinterpret_cast<unsigned*>(&h2);
    u.w = *reinterpret_cast<unsigned*>(&h3);
    reinterpret_cast<uint4*>(g_bufC)[i] = u;
}

// ---------------------------------------------------------------------------
// hist + position in ONE atomic pass: pos[e] = cnt[row[e]]++ .
// ---------------------------------------------------------------------------
__global__ void hist_pos_kernel(const int4* __restrict__ rows4) {
    int t = blockIdx.x * blockDim.x + threadIdx.x;
    if (t >= NNZ / 4) return;
    int4 r = rows4[t];
    int4 p;
    p.x = atomicAdd(&g_cnt[r.x], 1);
    p.y = atomicAdd(&g_cnt[r.y], 1);
    p.z = atomicAdd(&g_cnt[r.z], 1);
    p.w = atomicAdd(&g_cnt[r.w], 1);
    reinterpret_cast<int4*>(g_pos)[t] = p;
}

// ---------------------------------------------------------------------------
// Single-pass exclusive scan (decoupled lookback), shuffle-based block scan.
// All NBLK=118 blocks co-resident (148 SMs) — spin cannot deadlock.
// ---------------------------------------------------------------------------
__global__ void scan_fused_kernel() {
    __shared__ int s_warp[32];
    __shared__ int s_carry;
    int b = blockIdx.x, t = threadIdx.x;
    int lane = t & 31, w = t >> 5;
    int i = b * SCAN_BS + t;
    int v = (i < NTOT) ? g_cnt[i] : 0;

    int x = v;
    #pragma unroll
    for (int off = 1; off < 32; off <<= 1) {
        int n = __shfl_up_sync(0xFFFFFFFFu, x, off);
        if (lane >= off) x += n;
    }
    if (lane == 31) s_warp[w] = x;
    __syncthreads();
    if (w == 0) {
        int ws = s_warp[lane];
        #pragma unroll
        for (int off = 1; off < 32; off <<= 1) {
            int n = __shfl_up_sync(0xFFFFFFFFu, ws, off);
            if (lane >= off) ws += n;
        }
        s_warp[lane] = ws;
    }
    __syncthreads();
    int incl  = x + (w > 0 ? s_warp[w - 1] : 0);
    int total = s_warp[31];

    if (t == 0) {
        int ex = 0;
        if (b == 0) {
            atomicExch(&g_blk_desc[0],
                       ((unsigned long long)(unsigned)total << 32) | 2ull);
            g_rowptr[NTOT] = NNZ;
        } else {
            atomicExch(&g_blk_desc[b],
                       ((unsigned long long)(unsigned)total << 32) | 1ull);
            int p = b - 1;
            while (true) {
                unsigned long long d;
                do {
                    d = *((volatile unsigned long long*)&g_blk_desc[p]);
                } while ((d & 3ull) == 0ull);
                ex += (int)(d >> 32);
                if ((d & 3ull) == 2ull) break;
                --p;
            }
            atomicExch(&g_blk_desc[b],
                       ((unsigned long long)(unsigned)(ex + total) << 32) | 2ull);
        }
        s_carry = ex;
    }
    __syncthreads();

    if (i < NTOT) g_rowptr[i] = s_carry + incl - v;
}

// ---------------------------------------------------------------------------
// scatter (STREAMING, no atomics): g_sorted[rowptr[r] + pos[e]] = (col, val).
// ---------------------------------------------------------------------------
__global__ void scatter_kernel(const float4* __restrict__ vals4,
                               const int4*   __restrict__ rows4,
                               const int4*   __restrict__ cols4) {
    int t = blockIdx.x * blockDim.x + threadIdx.x;
    if (t >= NNZ / 4) return;
    int4   r = rows4[t];
    int4   c = cols4[t];
    float4 v = vals4[t];
    int4   p = reinterpret_cast<const int4*>(g_pos)[t];

    g_sorted[__ldg(&g_rowptr[r.x]) + p.x] = make_int2(c.x, __float_as_int(v.x));
    g_sorted[__ldg(&g_rowptr[r.y]) + p.y] = make_int2(c.y, __float_as_int(v.y));
    g_sorted[__ldg(&g_rowptr[r.z]) + p.z] = make_int2(c.z, __float_as_int(v.z));
    g_sorted[__ldg(&g_rowptr[r.w]) + p.w] = make_int2(c.w, __float_as_int(v.w));
}

// ---------------------------------------------------------------------------
// helpers
// ---------------------------------------------------------------------------
__device__ __forceinline__ uint2 f4_to_h4(float4 f) {
    __half2 h01 = __floats2half2_rn(f.x, f.y);
    __half2 h23 = __floats2half2_rn(f.z, f.w);
    uint2 u;
    u.x = *reinterpret_cast<unsigned*>(&h01);
    u.y = *reinterpret_cast<unsigned*>(&h23);
    return u;
}
// 8 halves (uint4) -> 8 floats, fma into accA/accB with scale v
__device__ __forceinline__ void h8_fma(float4& accA, float4& accB, uint4 u, float v) {
    __half2 h0 = *reinterpret_cast<__half2*>(&u.x);
    __half2 h1 = *reinterpret_cast<__half2*>(&u.y);
    __half2 h2 = *reinterpret_cast<__half2*>(&u.z);
    __half2 h3 = *reinterpret_cast<__half2*>(&u.w);
    float2 f0 = __half22float2(h0), f1 = __half22float2(h1);
    float2 f2 = __half22float2(h2), f3 = __half22float2(h3);
    accA.x += v * f0.x; accA.y += v * f0.y; accA.z += v * f1.x; accA.w += v * f1.y;
    accB.x += v * f2.x; accB.y += v * f2.y; accB.z += v * f3.x; accB.w += v * f3.y;
}

// ---------------------------------------------------------------------------
// All layers: gather fp16, 8 lanes/row (16B/lane), 4 rows per warp.
// Unroll-2 with paired int4 meta loads.
// mode 0: store fp16 y (uint4/thread).
// mode 1: out = (pB + pA + acc) / 3  (fp32, 2x float4 per thread)
// ---------------------------------------------------------------------------
__global__ void spmm_kernel(const __half* __restrict__ x,
                            __half*       __restrict__ y,
                            const __half* __restrict__ pB,
                            const __half* __restrict__ pA,
                            float4*       __restrict__ out4,
                            int mode) {
    int t = blockIdx.x * blockDim.x + threadIdx.x;
    if (t >= NTOT * 8) return;
    int r = t >> 3;
    int c = (t & 7) * 8;           // column offset in halves (8 per lane)

    int beg = __ldg(&g_rowptr[r]);
    int end = __ldg(&g_rowptr[r + 1]);

    float4 a0A = make_float4(0.f, 0.f, 0.f, 0.f);
    float4 a0B = make_float4(0.f, 0.f, 0.f, 0.f);
    float4 a1A = make_float4(0.f, 0.f, 0.f, 0.f);
    float4 a1B = make_float4(0.f, 0.f, 0.f, 0.f);

    int k = beg;
    if (k < end && (k & 1)) {
        int2 m = __ldg(&g_sorted[k]);
        uint4 u = *reinterpret_cast<const uint4*>(x + (size_t)m.x * EMB + c);
        h8_fma(a0A, a0B, u, __int_as_float(m.y));
        ++k;
    }
    for (; k + 2 <= end; k += 2) {
        int4 mm = __ldg(reinterpret_cast<const int4*>(&g_sorted[k]));
        uint4 u0 = *reinterpret_cast<const uint4*>(x + (size_t)mm.x * EMB + c);
        uint4 u1 = *reinterpret_cast<const uint4*>(x + (size_t)mm.z * EMB + c);
        h8_fma(a0A, a0B, u0, __int_as_float(mm.y));
        h8_fma(a1A, a1B, u1, __int_as_float(mm.w));
    }
    if (k < end) {
        int2 m = __ldg(&g_sorted[k]);
        uint4 u = *reinterpret_cast<const uint4*>(x + (size_t)m.x * EMB + c);
        h8_fma(a0A, a0B, u, __int_as_float(m.y));
    }

    float4 accA, accB;
    accA.x = a0A.x + a1A.x; accA.y = a0A.y + a1A.y;
    accA.z = a0A.z + a1A.z; accA.w = a0A.w + a1A.w;
    accB.x = a0B.x + a1B.x; accB.y = a0B.y + a1B.y;
    accB.z = a0B.z + a1B.z; accB.w = a0B.w + a1B.w;

    if (mode == 0) {
        uint2 lo = f4_to_h4(accA);
        uint2 hi = f4_to_h4(accB);
        uint4 st; st.x = lo.x; st.y = lo.y; st.z = hi.x; st.w = hi.y;
        reinterpret_cast<uint4*>(y)[t] = st;
    } else {
        uint4 ub = reinterpret_cast<const uint4*>(pB)[t];
        uint4 ua = reinterpret_cast<const uint4*>(pA)[t];
        float4 bA = make_float4(0.f,0.f,0.f,0.f), bB = make_float4(0.f,0.f,0.f,0.f);
        float4 aA = make_float4(0.f,0.f,0.f,0.f), aB = make_float4(0.f,0.f,0.f,0.f);
        h8_fma(bA, bB, ub, 1.0f);
        h8_fma(aA, aB, ua, 1.0f);
        const float inv3 = 1.0f / 3.0f;
        float4 r0, r1;
        r0.x = (bA.x + aA.x + accA.x) * inv3;
        r0.y = (bA.y + aA.y + accA.y) * inv3;
        r0.z = (bA.z + aA.z + accA.z) * inv3;
        r0.w = (bA.w + aA.w + accA.w) * inv3;
        r1.x = (bB.x + aB.x + accB.x) * inv3;
        r1.y = (bB.y + aB.y + accB.y) * inv3;
        r1.z = (bB.z + aB.z + accB.z) * inv3;
        r1.w = (bB.w + aB.w + accB.w) * inv3;
        size_t o = (size_t)r * 16 + (size_t)(t & 7) * 2;
        out4[o]     = r0;
        out4[o + 1] = r1;
    }
}

// ---------------------------------------------------------------------------
// launch: 7 kernel launches, trivially graph-capturable.
// ---------------------------------------------------------------------------
extern "C" void kernel_launch(void* const* d_in, const int* in_sizes, int n_in,
                              void* d_out, int out_size) {
    const float* user_emb = (const float*)d_in[0];
    const float* item_emb = (const float*)d_in[1];
    const float* adj_vals = (const float*)d_in[2];
    const int*   adj_rows = (const int*)d_in[3];
    const int*   adj_cols = (const int*)d_in[4];
    float4* out = (float4*)d_out;

    __half *A, *B, *C;
    cudaGetSymbolAddress((void**)&A, g_bufA);
    cudaGetSymbolAddress((void**)&B, g_bufB);
    cudaGetSymbolAddress((void**)&C, g_bufC);

    const int TB = 256;
    const int gridC  = (TOTAL_F / 8 + TB - 1) / TB;   // 3750 (covers NTOT & NBLK too)
    const int gridE4 = (NNZ / 4 + TB - 1) / TB;       // 1172
    const int gridS  = (NTOT * 8 + TB - 1) / TB;      // 3750

    // convert inputs to fp16 + zero counters; then CSR build
    convert_zero_kernel<<<gridC, TB>>>((const float4*)user_emb,
                                       (const float4*)item_emb);
    hist_pos_kernel<<<gridE4, TB>>>((const int4*)adj_rows);
    scan_fused_kernel<<<NBLK, SCAN_BS>>>();
    scatter_kernel<<<gridE4, TB>>>((const float4*)adj_vals,
                                   (const int4*)adj_rows,
                                   (const int4*)adj_cols);

    // Layer 0: C -> B
    spmm_kernel<<<gridS, TB>>>(C, B, nullptr, nullptr, nullptr, 0);
    // Layer 1: B -> A
    spmm_kernel<<<gridS, TB>>>(B, A, nullptr, nullptr, nullptr, 0);
    // Layer 2: A -> acc ; out = (B + A + acc)/3  (fp32, single write)
    spmm_kernel<<<gridS, TB>>>(A, nullptr, B, A, out, 1);
}